// round 6
// baseline (speedup 1.0000x reference)
#include <cuda_runtime.h>
#include <stdint.h>

// Graph2Col: stable stream compaction — single-pass decoupled lookback.
// Input : mapping [128, 2048, 32] int32, -1 = empty. total = 8388608.
// Output float32 buffer of 5*total elements:
//   [0, 2*total)        nodes [total,2] : (row, value)      or (-1,-1)
//   [2*total, 5*total)  cols  [total,3] : (row, vert, reg)  or (-1,-1,-1)
// Valid entries compacted to front in row-major order. Padding rows are all
// -1 and therefore order-free: invalid element with exclusive-valid-prefix p
// at flat index i goes to slot total-1-(i-p)  (bijection onto [n_valid,total)).

#define CHUNK      4096
#define NTHREADS   256
#define NWARPS     (NTHREADS / 32)      // 8
#define WELEMS     (CHUNK / NWARPS)     // 512 elements per warp
#define ITERS      (WELEMS / 32)        // 16
#define MAX_BLOCKS 8192

// Tile state: one 32-bit word = (flag << 30) | count.
// flag: 0 = empty, 1 = aggregate published, 2 = inclusive prefix published.
// count fits in 24 bits (max total = 2^23). Single-word -> no fence needed.
#define FLAG_AGG 1
#define FLAG_INC 2

__device__ int g_state[MAX_BLOCKS];
__device__ int g_ticket;

__global__ void __launch_bounds__(NTHREADS)
init_kernel(int nblocks) {
    const int i = blockIdx.x * NTHREADS + threadIdx.x;
    if (i < nblocks) g_state[i] = 0;
    if (i == 0) g_ticket = 0;
}

__device__ __forceinline__ int ld_state(int idx) {
    return *(volatile int*)&g_state[idx];
}

template <int LAYOUT>   // 0: float32 (confirmed). 1: int64. 2: int32+int64.
__global__ void __launch_bounds__(NTHREADS)
scatter_kernel(const int* __restrict__ map, void* __restrict__ outv, int total) {
    const int tid  = threadIdx.x;
    const int lane = tid & 31;
    const int wid  = tid >> 5;
    const unsigned below = (1u << lane) - 1u;

    __shared__ int s_tile;
    __shared__ int s_excl;
    __shared__ int s_wsum[NWARPS];

    if (tid == 0) s_tile = atomicAdd(&g_ticket, 1);   // tile order = arrival order
    __syncthreads();
    const int tile = s_tile;
    const int wElemBase = tile * CHUNK + wid * WELEMS;

    // ---- load + per-warp ballots ----
    int vals[ITERS];
    unsigned masks[ITERS];
    int c = 0;
    #pragma unroll
    for (int k = 0; k < ITERS; k++) {
        const int i = wElemBase + 32 * k + lane;
        vals[k] = (i < total) ? __ldg(map + i) : -1;
        const bool ok = (i < total) && (vals[k] != -1);
        masks[k] = __ballot_sync(0xffffffffu, ok);
        c += __popc(masks[k]);   // warp-uniform
    }
    if (lane == 0) s_wsum[wid] = c;
    __syncthreads();

    // ---- warp 0: decoupled lookback ----
    if (wid == 0) {
        int agg = 0;
        #pragma unroll
        for (int w = 0; w < NWARPS; w++) agg += s_wsum[w];

        int excl = 0;
        if (tile == 0) {
            if (lane == 0) atomicExch(&g_state[0], (FLAG_INC << 30) | agg);
        } else {
            if (lane == 0) atomicExch(&g_state[tile], (FLAG_AGG << 30) | agg);
            int base = tile - 1;           // window: idx = base - lane, lane 0 nearest
            int running = 0;
            while (true) {
                const int idx = base - lane;
                const int s = (idx >= 0) ? ld_state(idx) : (FLAG_INC << 30);
                const int flag = (unsigned)s >> 30;
                const int val  = s & 0xffffff;
                const unsigned done = __ballot_sync(0xffffffffu, flag == FLAG_INC);
                const unsigned zero = __ballot_sync(0xffffffffu, flag == 0);
                if (done) {
                    const int d = __ffs(done) - 1;       // closest inclusive
                    if ((zero & ((1u << d) - 1u)) == 0) {
                        const int contrib = (lane <= d) ? val : 0;
                        running += __reduce_add_sync(0xffffffffu, contrib);
                        break;
                    }
                } else if (!zero) {
                    running += __reduce_add_sync(0xffffffffu, val);
                    base -= 32;
                    continue;
                }
                __nanosleep(40);
            }
            excl = running;
            if (lane == 0)
                atomicExch(&g_state[tile], (FLAG_INC << 30) | (excl + agg));
        }
        if (lane == 0) s_excl = excl;
    }
    __syncthreads();

    // ---- per-warp base offset ----
    int wpref = 0;
    #pragma unroll
    for (int w = 0; w < NWARPS; w++) wpref += (w < wid) ? s_wsum[w] : 0;
    int wbase = s_excl + wpref;

    // ---- scatter ----
    #pragma unroll
    for (int k = 0; k < ITERS; k++) {
        const int ibase = wElemBase + 32 * k;
        const unsigned m = masks[k];

        if (LAYOUT == 0 && m == 0xffffffffu) {
            // FAST PATH: 32 consecutive valid -> fully dense, coalesced writes.
            float* out  = (float*)outv;
            float* cols = out + 2LL * (long long)total;
            // nodes: float2 per element, lane l handles i = ibase + l
            {
                const int i = ibase + lane;
                float2 n2;
                n2.x = (float)(i >> 16);
                n2.y = (float)vals[k];
                reinterpret_cast<float2*>(out)[wbase + lane] = n2;
            }
            // cols: 96 contiguous floats at 3*wbase; value is a pure
            // function of flat index -> no inter-lane data exchange.
            const int cb = 3 * wbase;
            #pragma unroll
            for (int s = 0; s < 3; s++) {
                const int j    = s * 32 + lane;     // 0..95
                const int e    = j / 3;
                const int comp = j - 3 * e;         // j % 3
                const int i    = ibase + e;
                int cv;
                if (comp == 0)      cv = i >> 16;           // row
                else if (comp == 1) cv = (i >> 5) & 2047;   // vert
                else                cv = i & 31;            // reg
                cols[cb + j] = (float)cv;
            }
            wbase += 32;
            continue;
        }

        // SLOW PATH: scattered per-element writes.
        const int i     = ibase + lane;
        const int rank  = __popc(m & below);
        const int pexcl = wbase + rank;
        const bool ok   = (m >> lane) & 1u;
        if (i < total) {
            const int q    = ok ? pexcl : (total - 1 - (i - pexcl));
            const int row  = i >> 16;
            const int vert = (i >> 5) & 2047;
            const int reg  = i & 31;
            const int v    = vals[k];
            if (LAYOUT == 0) {
                float* out  = (float*)outv;
                float* cols = out + 2LL * (long long)total;
                float2 n2;
                n2.x = ok ? (float)row : -1.0f;
                n2.y = ok ? (float)v   : -1.0f;
                reinterpret_cast<float2*>(out)[q] = n2;
                float* cp = cols + 3LL * q;
                cp[0] = ok ? (float)row  : -1.0f;
                cp[1] = ok ? (float)vert : -1.0f;
                cp[2] = ok ? (float)reg  : -1.0f;
            } else if (LAYOUT == 1) {
                long long* out  = (long long*)outv;
                long long* cols = out + 2LL * (long long)total;
                longlong2 n2;
                n2.x = ok ? (long long)row : -1LL;
                n2.y = ok ? (long long)v   : -1LL;
                reinterpret_cast<longlong2*>(out)[q] = n2;
                long long* cp = cols + 3LL * q;
                cp[0] = ok ? (long long)row  : -1LL;
                cp[1] = ok ? (long long)vert : -1LL;
                cp[2] = ok ? (long long)reg  : -1LL;
            } else {
                int* out = (int*)outv;
                int2 n2;
                n2.x = ok ? row : -1;
                n2.y = ok ? v   : -1;
                reinterpret_cast<int2*>(out)[q] = n2;
                long long* cols = (long long*)((char*)outv + 8LL * (long long)total);
                long long* cp = cols + 3LL * q;
                cp[0] = ok ? (long long)row  : -1LL;
                cp[1] = ok ? (long long)vert : -1LL;
                cp[2] = ok ? (long long)reg  : -1LL;
            }
        }
        wbase += __popc(m);
    }
}

extern "C" void kernel_launch(void* const* d_in, const int* in_sizes, int n_in,
                              void* d_out, int out_size) {
    const int* map     = (const int*)d_in[0];
    const int  total   = in_sizes[0];                 // 8388608
    const int  nblocks = (total + CHUNK - 1) / CHUNK; // 2048

    init_kernel<<<(nblocks + NTHREADS - 1) / NTHREADS, NTHREADS>>>(nblocks);

    const long long T = total;
    if ((long long)out_size == 5 * T) {
        scatter_kernel<0><<<nblocks, NTHREADS>>>(map, d_out, total);
    } else if ((long long)out_size == 8 * T) {
        scatter_kernel<2><<<nblocks, NTHREADS>>>(map, d_out, total);
    } else {
        scatter_kernel<1><<<nblocks, NTHREADS>>>(map, d_out, total);
    }
}

// round 9
// speedup vs baseline: 1.0320x; 1.0320x over previous
#include <cuda_runtime.h>
#include <stdint.h>

// Graph2Col: stable stream compaction — single-pass decoupled lookback, v2.
// Input : mapping [128, 2048, 32] int32, -1 = empty. total = 8388608.
// Output float32 buffer of 5*total elements:
//   [0, 2*total)        nodes [total,2] : (row, value)      or (-1,-1)
//   [2*total, 5*total)  cols  [total,3] : (row, vert, reg)  or (-1,-1,-1)
// Invalid slots are order-free (all -1): element with exclusive-valid-prefix
// p at flat index i goes to slot total-1-(i-p) (bijection onto [n_valid,total)).

#define CHUNK      8192
#define NTHREADS   512
#define NWARPS     (NTHREADS / 32)      // 16
#define WELEMS     (CHUNK / NWARPS)     // 512 elements per warp
#define ITERS      (WELEMS / 32)        // 16
#define MAX_TILES  4096

// Tile state word = (flag << 30) | count.  count <= 2^23 -> single word, no fence.
#define FLAG_AGG 1
#define FLAG_INC 2

__device__ int g_state[MAX_TILES];
__device__ int g_ticket;

__global__ void __launch_bounds__(256)
init_kernel(int ntiles) {
    const int i = blockIdx.x * 256 + threadIdx.x;
    if (i < ntiles) g_state[i] = 0;
    if (i == 0) g_ticket = 0;
}

__device__ __forceinline__ int ld_state(int idx) {
    return *(volatile int*)&g_state[idx];
}

template <int LAYOUT>   // 0: float32 (confirmed). 1: int64. 2: int32+int64.
__global__ void __launch_bounds__(NTHREADS)
scatter_kernel(const int* __restrict__ map, void* __restrict__ outv, int total) {
    const int tid  = threadIdx.x;
    const int lane = tid & 31;
    const int wid  = tid >> 5;
    const unsigned below = (1u << lane) - 1u;

    __shared__ int s_tile;
    __shared__ int s_excl;
    __shared__ int s_wsum[NWARPS];

    if (tid == 0) s_tile = atomicAdd(&g_ticket, 1);   // tile order = arrival order
    __syncthreads();
    const int tile = s_tile;
    const int wElemBase = tile * CHUNK + wid * WELEMS;

    // ---- load (16-deep MLP, overlaps predecessors' lookback publishing) ----
    int vals[ITERS];
    unsigned masks[ITERS];
    int c = 0;
    #pragma unroll
    for (int k = 0; k < ITERS; k++) {
        const int i = wElemBase + 32 * k + lane;
        vals[k] = (i < total) ? __ldg(map + i) : -1;
        const bool ok = (i < total) && (vals[k] != -1);
        masks[k] = __ballot_sync(0xffffffffu, ok);
        c += __popc(masks[k]);   // warp-uniform
    }
    if (lane == 0) s_wsum[wid] = c;
    __syncthreads();

    // ---- warp 0: decoupled lookback ----
    if (wid == 0) {
        int agg = 0;
        #pragma unroll
        for (int w = 0; w < NWARPS; w++) agg += s_wsum[w];

        int excl = 0;
        if (tile == 0) {
            if (lane == 0) atomicExch(&g_state[0], (FLAG_INC << 30) | agg);
        } else {
            if (lane == 0) atomicExch(&g_state[tile], (FLAG_AGG << 30) | agg);
            int base = tile - 1;           // window idx = base - lane
            int running = 0;
            while (true) {
                const int idx  = base - lane;
                const int s    = (idx >= 0) ? ld_state(idx) : (FLAG_INC << 30);
                const int flag = (unsigned)s >> 30;
                const int val  = s & 0xffffff;
                const unsigned done = __ballot_sync(0xffffffffu, flag == FLAG_INC);
                const unsigned zero = __ballot_sync(0xffffffffu, flag == 0);
                if (done) {
                    const int d = __ffs(done) - 1;            // nearest inclusive
                    if ((zero & ((1u << d) - 1u)) == 0) {
                        running += __reduce_add_sync(0xffffffffu, (lane <= d) ? val : 0);
                        break;
                    }
                } else if (!zero) {
                    running += __reduce_add_sync(0xffffffffu, val);
                    base -= 32;
                    continue;
                }
                __nanosleep(20);
            }
            excl = running;
            if (lane == 0)
                atomicExch(&g_state[tile], (FLAG_INC << 30) | (excl + agg));
        }
        if (lane == 0) s_excl = excl;
    }
    __syncthreads();

    int wpref = 0;
    #pragma unroll
    for (int w = 0; w < NWARPS; w++) wpref += (w < wid) ? s_wsum[w] : 0;
    int wbase = s_excl + wpref;

    // ---- scatter ----
    float* const outF  = (float*)outv;
    float* const colsF = outF + 2LL * (long long)total;

    #pragma unroll
    for (int k = 0; k < ITERS; k++) {
        const int ibase = wElemBase + 32 * k;    // multiple of 32
        const unsigned m = masks[k];

        if (LAYOUT == 0 && m == 0xffffffffu) {
            // FAST PATH: 32-aligned dense block => row/vert warp-uniform.
            const int   rowI  = ibase >> 16;
            const float rowF  = (float)rowI;
            const float vertF = (float)((ibase >> 5) & 2047);
            // nodes: one coalesced STG.64 run
            {
                float2 n2;
                n2.x = rowF;
                n2.y = (float)vals[k];
                reinterpret_cast<float2*>(outF)[wbase + lane] = n2;
            }
            // cols: 96 contiguous floats, 3 stride-1 STG.32
            const int cb = 3 * wbase;
            #pragma unroll
            for (int s = 0; s < 3; s++) {
                const int j    = s * 32 + lane;          // 0..95
                const int e    = (j * 21846) >> 16;      // j / 3
                const int comp = j - 3 * e;              // j % 3
                const float cv = (comp == 0) ? rowF
                               : (comp == 1) ? vertF
                                             : (float)e; // reg = e (aligned block)
                colsF[cb + j] = cv;
            }
            wbase += 32;
            continue;
        }

        // SLOW PATH (rare): scattered per-element writes.
        const int i     = ibase + lane;
        const int rank  = __popc(m & below);
        const int pexcl = wbase + rank;
        const bool ok   = (m >> lane) & 1u;
        if (i < total) {
            const int q    = ok ? pexcl : (total - 1 - (i - pexcl));
            const int row  = i >> 16;
            const int vert = (i >> 5) & 2047;
            const int reg  = i & 31;
            const int v    = vals[k];
            if (LAYOUT == 0) {
                float2 n2;
                n2.x = ok ? (float)row : -1.0f;
                n2.y = ok ? (float)v   : -1.0f;
                reinterpret_cast<float2*>(outF)[q] = n2;
                float* cp = colsF + 3LL * q;
                cp[0] = ok ? (float)row  : -1.0f;
                cp[1] = ok ? (float)vert : -1.0f;
                cp[2] = ok ? (float)reg  : -1.0f;
            } else if (LAYOUT == 1) {
                long long* out  = (long long*)outv;
                long long* cols = out + 2LL * (long long)total;
                longlong2 n2;
                n2.x = ok ? (long long)row : -1LL;
                n2.y = ok ? (long long)v   : -1LL;
                reinterpret_cast<longlong2*>(out)[q] = n2;
                long long* cp = cols + 3LL * q;
                cp[0] = ok ? (long long)row  : -1LL;
                cp[1] = ok ? (long long)vert : -1LL;
                cp[2] = ok ? (long long)reg  : -1LL;
            } else {
                int* out = (int*)outv;
                int2 n2;
                n2.x = ok ? row : -1;
                n2.y = ok ? v   : -1;
                reinterpret_cast<int2*>(out)[q] = n2;
                long long* cols = (long long*)((char*)outv + 8LL * (long long)total);
                long long* cp = cols + 3LL * q;
                cp[0] = ok ? (long long)row  : -1LL;
                cp[1] = ok ? (long long)vert : -1LL;
                cp[2] = ok ? (long long)reg  : -1LL;
            }
        }
        wbase += __popc(m);
    }
}

extern "C" void kernel_launch(void* const* d_in, const int* in_sizes, int n_in,
                              void* d_out, int out_size) {
    const int* map    = (const int*)d_in[0];
    const int  total  = in_sizes[0];                 // 8388608
    const int  ntiles = (total + CHUNK - 1) / CHUNK; // 1024

    init_kernel<<<(ntiles + 255) / 256, 256>>>(ntiles);

    const long long T = total;
    if ((long long)out_size == 5 * T) {
        scatter_kernel<0><<<ntiles, NTHREADS>>>(map, d_out, total);
    } else if ((long long)out_size == 8 * T) {
        scatter_kernel<2><<<ntiles, NTHREADS>>>(map, d_out, total);
    } else {
        scatter_kernel<1><<<ntiles, NTHREADS>>>(map, d_out, total);
    }
}